// round 1
// baseline (speedup 1.0000x reference)
#include <cuda_runtime.h>

#define T_DIM 2048
#define MAX_B 8192
#define FULLMASK 0xffffffffu

// Per-row loss scratch (no allocations allowed in kernel_launch).
__device__ float g_per_row[MAX_B];

// One warp per row.
//  - ballot-scan labels in 32-wide chunks to find ind0 (first change point);
//    expected 1 chunk for random labels, general path loops to T.
//  - warp-parallel masked prefix-product scan computes dd2 over [0, L)
//    (L = ind0 if change else T), matching the reference's fp32 cumprod.
//  - lane 0 computes the W=8 delay-detection window serially and writes
//    the per-row loss.
__global__ void per_row_kernel(const float* __restrict__ outputs,
                               const int* __restrict__ labels,
                               int B) {
    int gw   = (blockIdx.x * blockDim.x + threadIdx.x) >> 5;  // global warp = row
    int lane = threadIdx.x & 31;
    if (gw >= B) return;

    const float* p   = outputs + (size_t)gw * T_DIM;
    const int*   lab = labels  + (size_t)gw * T_DIM;

    // ---- find ind0 = first k with lab[k] != lab[0] ----
    int ind0 = T_DIM;
    int lab0 = 0;
    for (int base = 0; base < T_DIM; base += 32) {
        int v = lab[base + lane];
        if (base == 0) lab0 = __shfl_sync(FULLMASK, v, 0);
        unsigned m = __ballot_sync(FULLMASK, v != lab0);
        if (m) { ind0 = base + (__ffs(m) - 1); break; }
    }
    const bool has_change = (ind0 < T_DIM);
    const int  L = has_change ? ind0 : T_DIM;   // prefix length for false-alarm term

    // ---- dd2 prefix: S = sum_{k<L} (k+1) * p[k] * prod_{j<k}(1 - p[j]) ----
    float S = 0.0f;   // running sum (consistent across lanes via xor-reduce)
    float P = 1.0f;   // running product carried across 32-chunks
    for (int base = 0; base < L; base += 32) {
        int   k  = base + lane;
        float pk = (k < L) ? p[k] : 0.0f;   // masked -> factor 1, term 0
        float q  = 1.0f - pk;

        // warp inclusive product scan of q
        float incl = q;
        #pragma unroll
        for (int o = 1; o < 32; o <<= 1) {
            float u = __shfl_up_sync(FULLMASK, incl, o);
            if (lane >= o) incl *= u;
        }
        float excl = __shfl_up_sync(FULLMASK, incl, 1);
        if (lane == 0) excl = 1.0f;

        float contrib = (k < L) ? (float)(k + 1) * pk * (P * excl) : 0.0f;
        #pragma unroll
        for (int o = 16; o > 0; o >>= 1)
            contrib += __shfl_xor_sync(FULLMASK, contrib, o);
        S += contrib;

        P *= __shfl_sync(FULLMASK, incl, 31);  // chunk total product
    }

    if (lane == 0) {
        float fa = 1.0f - S;
        float per;
        if (has_change) {
            // delay-detection window: outputs[ind0 : ind0 + min(8, T-ind0)]
            int n = T_DIM - ind0; if (n > 8) n = 8;
            float cp = 1.0f, term1 = 0.0f, cpl = 1.0f, pl = 0.0f;
            for (int kk = 0; kk < n; kk++) {
                float pw = p[ind0 + kk];
                term1 += (float)(kk + 1) * pw * cp;
                if (kk == n - 1) { cpl = cp; pl = pw; }
                cp *= (1.0f - pw);
            }
            // dd = term1 + n * (W+1) * cp[n-1] * (1 - p[n-1]),  W+1 = 9
            float dd = term1 + (float)n * 9.0f * cpl * (1.0f - pl);
            per = 0.5f * dd + 0.5f * fa;   // ALPHA = 0.5
        } else {
            per = fa;
        }
        g_per_row[gw] = per;
    }
}

// Deterministic single-block tree reduce -> mean.
__global__ void reduce_kernel(float* __restrict__ out, int B) {
    __shared__ float sh[256];
    float s = 0.0f;
    for (int i = threadIdx.x; i < B; i += 256) s += g_per_row[i];
    sh[threadIdx.x] = s;
    __syncthreads();
    #pragma unroll
    for (int st = 128; st > 0; st >>= 1) {
        if (threadIdx.x < st) sh[threadIdx.x] += sh[threadIdx.x + st];
        __syncthreads();
    }
    if (threadIdx.x == 0) out[0] = sh[0] / (float)B;
}

extern "C" void kernel_launch(void* const* d_in, const int* in_sizes, int n_in,
                              void* d_out, int out_size) {
    const float* outputs = (const float*)d_in[0];
    const int*   labels  = (const int*)d_in[1];

    int B = in_sizes[0] / T_DIM;
    if (B > MAX_B) B = MAX_B;

    const int threads = 256;                       // 8 warps/block -> 8 rows/block
    int blocks = (B * 32 + threads - 1) / threads;

    per_row_kernel<<<blocks, threads>>>(outputs, labels, B);
    reduce_kernel<<<1, 256>>>((float*)d_out, B);
}

// round 2
// speedup vs baseline: 1.0467x; 1.0467x over previous
#include <cuda_runtime.h>

#define T_DIM 2048
#define MAX_B 8192
#define NTHREADS 256
#define WARPS_PER_BLOCK (NTHREADS / 32)
#define FULLMASK 0xffffffffu

// Scratch (no allocations allowed): per-block partials + completion counter.
__device__ float g_partials[(MAX_B * 32) / NTHREADS + 1];
__device__ int   g_counter = 0;   // reset to 0 by last block each run -> graph-replay safe

// One warp per row, fully fused: row loss -> block partial -> last block reduces.
__global__ void fused_loss_kernel(const float* __restrict__ outputs,
                                  const int* __restrict__ labels,
                                  float* __restrict__ out, int B) {
    const int gw   = (blockIdx.x * blockDim.x + threadIdx.x) >> 5;  // row
    const int lane = threadIdx.x & 31;
    const int wid  = threadIdx.x >> 5;

    __shared__ float sh[NTHREADS];     // reused: warp losses, then final reduce
    __shared__ int   sh_last;

    float per = 0.0f;
    if (gw < B) {
        const float* p   = outputs + (size_t)gw * T_DIM;
        const int*   lab = labels  + (size_t)gw * T_DIM;

        // Issue BOTH first-chunk loads before any dependent work (one overlapped
        // DRAM round-trip instead of two serialized ones on the common path).
        const int   v0  = lab[lane];
        const float pw0 = p[lane];

        const int lab0 = __shfl_sync(FULLMASK, v0, 0);
        unsigned  m    = __ballot_sync(FULLMASK, v0 != lab0);

        int ind0 = T_DIM;
        if (m) {
            ind0 = __ffs(m) - 1;
        } else {
            for (int base = 32; base < T_DIM; base += 32) {
                int v = lab[base + lane];
                m = __ballot_sync(FULLMASK, v != lab0);
                if (m) { ind0 = base + (__ffs(m) - 1); break; }
            }
        }
        const bool has_change = (ind0 < T_DIM);
        const int  L = has_change ? ind0 : T_DIM;   // false-alarm prefix length

        // ---- dd2 prefix: S = sum_{k<L} (k+1) * p[k] * prod_{j<k}(1 - p[j]) ----
        float S = 0.0f;
        float P = 1.0f;
        for (int base = 0; base < L; base += 32) {
            const int k = base + lane;
            float pk = (base == 0) ? pw0 : ((k < L) ? p[k] : 0.0f);
            if (k >= L) pk = 0.0f;                   // masked: factor 1, term 0
            float q = 1.0f - pk;

            // warp inclusive product scan of q
            float incl = q;
            #pragma unroll
            for (int o = 1; o < 32; o <<= 1) {
                float u = __shfl_up_sync(FULLMASK, incl, o);
                if (lane >= o) incl *= u;
            }
            float excl = __shfl_up_sync(FULLMASK, incl, 1);
            if (lane == 0) excl = 1.0f;

            float contrib = (k < L) ? (float)(k + 1) * pk * (P * excl) : 0.0f;
            #pragma unroll
            for (int o = 16; o > 0; o >>= 1)
                contrib += __shfl_xor_sync(FULLMASK, contrib, o);
            S += contrib;

            P *= __shfl_sync(FULLMASK, incl, 31);
        }

        if (lane == 0) {
            const float fa = 1.0f - S;
            if (has_change) {
                // delay window outputs[ind0 : ind0 + min(8, T-ind0)] (L1-hot)
                int n = T_DIM - ind0; if (n > 8) n = 8;
                float cp = 1.0f, term1 = 0.0f, cpl = 1.0f, pl = 0.0f;
                for (int kk = 0; kk < n; kk++) {
                    float pw = p[ind0 + kk];
                    term1 += (float)(kk + 1) * pw * cp;
                    if (kk == n - 1) { cpl = cp; pl = pw; }
                    cp *= (1.0f - pw);
                }
                const float dd = term1 + (float)n * 9.0f * cpl * (1.0f - pl); // W+1=9
                per = 0.5f * dd + 0.5f * fa;                                  // ALPHA=0.5
            } else {
                per = fa;
            }
        }
    }

    // ---- block partial (fixed order -> deterministic) ----
    if (lane == 0) sh[wid] = per;
    __syncthreads();
    if (threadIdx.x == 0) {
        float s = 0.0f;
        #pragma unroll
        for (int i = 0; i < WARPS_PER_BLOCK; i++) s += sh[i];
        g_partials[blockIdx.x] = s;
        __threadfence();
        int t = atomicAdd(&g_counter, 1);
        sh_last = (t == (int)gridDim.x - 1);
    }
    __syncthreads();

    // ---- last block: sum partials in fixed index order -> deterministic mean ----
    if (sh_last) {
        float s = 0.0f;
        for (int i = threadIdx.x; i < (int)gridDim.x; i += NTHREADS)
            s += g_partials[i];                       // L2-hot, just written
        sh[threadIdx.x] = s;
        __syncthreads();
        #pragma unroll
        for (int st = NTHREADS / 2; st > 0; st >>= 1) {
            if (threadIdx.x < st) sh[threadIdx.x] += sh[threadIdx.x + st];
            __syncthreads();
        }
        if (threadIdx.x == 0) {
            out[0] = sh[0] / (float)B;
            g_counter = 0;                            // reset for next graph replay
        }
    }
}

extern "C" void kernel_launch(void* const* d_in, const int* in_sizes, int n_in,
                              void* d_out, int out_size) {
    const float* outputs = (const float*)d_in[0];
    const int*   labels  = (const int*)d_in[1];

    int B = in_sizes[0] / T_DIM;
    if (B > MAX_B) B = MAX_B;

    int blocks = (B * 32 + NTHREADS - 1) / NTHREADS;   // one warp per row
    fused_loss_kernel<<<blocks, NTHREADS>>>(outputs, labels, (float*)d_out, B);
}

// round 3
// speedup vs baseline: 1.2399x; 1.1845x over previous
#include <cuda_runtime.h>

#define T_DIM 2048
#define MAX_B 8192
#define BLOCK 64
#define FULLMASK 0xffffffffu

// Scratch (no allocations allowed): per-block partials + completion counter.
__device__ float g_partials[MAX_B / BLOCK + 1];
__device__ int   g_counter = 0;   // reset by last block each run -> graph-replay safe

// One THREAD per row. Common case (ind0 <= 8, P ~ 99.8%) runs entirely out of
// registers after a single overlapped DRAM round-trip (6 back-to-back LDGs).
__global__ void fused_loss_kernel(const float* __restrict__ outputs,
                                  const int* __restrict__ labels,
                                  float* __restrict__ out, int B) {
    const int row = blockIdx.x * BLOCK + threadIdx.x;

    float per = 0.0f;
    if (row < B) {
        const float* p   = outputs + (size_t)row * T_DIM;
        const int*   lab = labels  + (size_t)row * T_DIM;

        // ---- prefetch 8 labels + 16 outputs; all 6 LDGs in flight together ----
        const int4   l0 = __ldg((const int4*)(lab));
        const int4   l1 = __ldg((const int4*)(lab + 4));
        const float4 q0 = __ldg((const float4*)(p));
        const float4 q1 = __ldg((const float4*)(p + 4));
        const float4 q2 = __ldg((const float4*)(p + 8));
        const float4 q3 = __ldg((const float4*)(p + 12));

        // constant-indexed only -> stays in registers
        const float pf[16] = {q0.x,q0.y,q0.z,q0.w, q1.x,q1.y,q1.z,q1.w,
                              q2.x,q2.y,q2.z,q2.w, q3.x,q3.y,q3.z,q3.w};
        const int   la[8]  = {l0.x,l0.y,l0.z,l0.w, l1.x,l1.y,l1.z,l1.w};

        // ---- ind0 = first k with lab[k] != lab[0] ----
        const int lab0 = la[0];
        int ind0 = T_DIM;
        #pragma unroll
        for (int k = 7; k >= 1; k--)          // descending: smallest k wins
            if (la[k] != lab0) ind0 = k;

        if (ind0 == T_DIM) {                  // rare: scan the rest
            for (int base = 8; base < T_DIM; base += 4) {
                int4 v = __ldg((const int4*)(lab + base));
                if (v.x != lab0) { ind0 = base;     break; }
                if (v.y != lab0) { ind0 = base + 1; break; }
                if (v.z != lab0) { ind0 = base + 2; break; }
                if (v.w != lab0) { ind0 = base + 3; break; }
            }
        }

        if (ind0 <= 8) {
            // ---- FAST PATH: prefix [0,ind0) + window [ind0, ind0+8), n = 8 ----
            // everything in registers; one unrolled predicated pass over pf[16]
            float S = 0.f, cp = 1.f;                    // false-alarm prefix
            float term1 = 0.f, cpw = 1.f, cpl = 1.f, pl = 0.f;  // delay window
            #pragma unroll
            for (int k = 0; k < 16; k++) {
                const float pk = pf[k];
                if (k < ind0) {                         // dd2 prefix term
                    S  += (float)(k + 1) * pk * cp;
                    cp *= 1.f - pk;
                }
                if (k >= ind0 && k < ind0 + 8) {        // window term
                    const int kk = k - ind0;
                    term1 += (float)(kk + 1) * pk * cpw;
                    if (kk == 7) { cpl = cpw; pl = pk; }
                    cpw *= 1.f - pk;
                }
            }
            const float fa = 1.f - S;
            const float dd = term1 + 8.f * 9.f * cpl * (1.f - pl);  // n=8, W+1=9
            per = 0.5f * dd + 0.5f * fa;                            // ALPHA=0.5
        } else {
            // ---- RARE GENERAL PATH (direct loads; first lines L1-hot) ----
            const bool has_change = (ind0 < T_DIM);
            const int  L = has_change ? ind0 : T_DIM;
            float S = 0.f, cp = 1.f;
            for (int k = 0; k < L; k++) {
                const float pk = p[k];
                S  += (float)(k + 1) * pk * cp;
                cp *= 1.f - pk;
            }
            const float fa = 1.f - S;
            if (has_change) {
                int n = T_DIM - ind0; if (n > 8) n = 8;
                float cpw = 1.f, term1 = 0.f, cpl = 1.f, pl = 0.f;
                for (int kk = 0; kk < n; kk++) {
                    const float pk = p[ind0 + kk];
                    term1 += (float)(kk + 1) * pk * cpw;
                    if (kk == n - 1) { cpl = cpw; pl = pk; }
                    cpw *= 1.f - pk;
                }
                const float dd = term1 + (float)n * 9.f * cpl * (1.f - pl);
                per = 0.5f * dd + 0.5f * fa;
            } else {
                per = fa;
            }
        }
    }

    // ---- block partial (fixed-order tree -> deterministic) ----
    __shared__ float sh[BLOCK];
    __shared__ int   sh_last;
    sh[threadIdx.x] = per;
    __syncthreads();
    #pragma unroll
    for (int st = BLOCK / 2; st > 0; st >>= 1) {
        if (threadIdx.x < st) sh[threadIdx.x] += sh[threadIdx.x + st];
        __syncthreads();
    }
    if (threadIdx.x == 0) {
        g_partials[blockIdx.x] = sh[0];
        __threadfence();
        sh_last = (atomicAdd(&g_counter, 1) == (int)gridDim.x - 1);
    }
    __syncthreads();

    // ---- last arriving block: fixed-order reduce of partials -> mean ----
    if (sh_last) {
        float s = 0.f;
        for (int i = threadIdx.x; i < (int)gridDim.x; i += BLOCK)
            s += g_partials[i];                 // L2-hot, just written
        __syncthreads();                        // sh reuse hazard guard
        sh[threadIdx.x] = s;
        __syncthreads();
        #pragma unroll
        for (int st = BLOCK / 2; st > 0; st >>= 1) {
            if (threadIdx.x < st) sh[threadIdx.x] += sh[threadIdx.x + st];
            __syncthreads();
        }
        if (threadIdx.x == 0) {
            out[0] = sh[0] / (float)B;
            g_counter = 0;                      // reset for next graph replay
        }
    }
}

extern "C" void kernel_launch(void* const* d_in, const int* in_sizes, int n_in,
                              void* d_out, int out_size) {
    const float* outputs = (const float*)d_in[0];
    const int*   labels  = (const int*)d_in[1];

    int B = in_sizes[0] / T_DIM;
    if (B > MAX_B) B = MAX_B;

    int blocks = (B + BLOCK - 1) / BLOCK;     // one thread per row -> 128 blocks
    fused_loss_kernel<<<blocks, BLOCK>>>(outputs, labels, (float*)d_out, B);
}